// round 2
// baseline (speedup 1.0000x reference)
#include <cuda_runtime.h>
#include <cuda_bf16.h>
#include <cstdint>

// Inputs (metadata order):
//   d_in[0]: output  float32  [16, 512, 32000]  (B*S = 8192 rows, V = 32000)
//   d_in[1]: target  int32    [16, 512]   (JAX x64-disabled downcasts int64->int32)
// Output: scalar float32 = sum(mask ? -log(p_target) : 0) / sum(mask),
//         mask = (target != 0)

#define ROWS      8192
#define VOCAB     32000
#define NTHREADS  1024
#define RPT       (ROWS / NTHREADS)   // 8 rows per thread

__global__ __launch_bounds__(NTHREADS, 1)
void nll_gather_kernel(const float* __restrict__ out_probs,
                       const int* __restrict__ target,
                       float* __restrict__ result)
{
    const int tid = threadIdx.x;

    // Each thread handles RPT rows, strided so target loads coalesce.
    int t[RPT];
    #pragma unroll
    for (int r = 0; r < RPT; ++r) {
        t[r] = target[tid + r * NTHREADS];
    }

    // Issue all gathers back-to-back for max MLP.
    float p[RPT];
    #pragma unroll
    for (int r = 0; r < RPT; ++r) {
        const int row = tid + r * NTHREADS;
        p[r] = __ldg(&out_probs[(size_t)row * VOCAB + t[r]]);
    }

    float lsum = 0.0f;
    float lcnt = 0.0f;
    #pragma unroll
    for (int r = 0; r < RPT; ++r) {
        if (t[r] != 0) {
            lsum += -__logf(p[r]);
            lcnt += 1.0f;
        }
    }

    // Warp reduction
    #pragma unroll
    for (int off = 16; off > 0; off >>= 1) {
        lsum += __shfl_down_sync(0xFFFFFFFFu, lsum, off);
        lcnt += __shfl_down_sync(0xFFFFFFFFu, lcnt, off);
    }

    __shared__ float s_sum[NTHREADS / 32];
    __shared__ float s_cnt[NTHREADS / 32];
    const int warp = tid >> 5;
    const int lane = tid & 31;
    if (lane == 0) {
        s_sum[warp] = lsum;
        s_cnt[warp] = lcnt;
    }
    __syncthreads();

    if (warp == 0) {
        float vs = (lane < NTHREADS / 32) ? s_sum[lane] : 0.0f;
        float vc = (lane < NTHREADS / 32) ? s_cnt[lane] : 0.0f;
        #pragma unroll
        for (int off = 16; off > 0; off >>= 1) {
            vs += __shfl_down_sync(0xFFFFFFFFu, vs, off);
            vc += __shfl_down_sync(0xFFFFFFFFu, vc, off);
        }
        if (lane == 0) {
            result[0] = vs / vc;
        }
    }
}

extern "C" void kernel_launch(void* const* d_in, const int* in_sizes, int n_in,
                              void* d_out, int out_size)
{
    const float* probs  = (const float*)d_in[0];
    const int*   target = (const int*)d_in[1];
    float*       result = (float*)d_out;

    nll_gather_kernel<<<1, NTHREADS>>>(probs, target, result);
}

// round 3
// speedup vs baseline: 1.5654x; 1.5654x over previous
#include <cuda_runtime.h>
#include <cuda_bf16.h>
#include <cstdint>

// Inputs (metadata order):
//   d_in[0]: output  float32  [16, 512, 32000]  (B*S = 8192 rows, V = 32000)
//   d_in[1]: target  int32    [16, 512]
// Output: scalar float32 = sum(target!=0 ? -log(p_target) : 0) / count(target!=0)

#define ROWS     8192
#define VOCAB    32000
#define NBLOCKS  64
#define NTHREADS 128          // rows per block = NTHREADS (1 row/thread)

__device__ float    g_sum[NBLOCKS];
__device__ float    g_cnt[NBLOCKS];
__device__ unsigned g_ticket;   // zero-initialized; finalizer resets to 0

__global__ __launch_bounds__(NTHREADS, 1)
void nll_gather_kernel(const float* __restrict__ out_probs,
                       const int* __restrict__ target,
                       float* __restrict__ result)
{
    const int tid = threadIdx.x;
    const int bid = blockIdx.x;
    const int row = bid * NTHREADS + tid;

    // Dependent chain: target load -> gather
    const int t = target[row];
    const float p = __ldg(&out_probs[(size_t)row * VOCAB + t]);

    float lsum = (t != 0) ? -__logf(p) : 0.0f;
    float lcnt = (t != 0) ? 1.0f : 0.0f;

    // Warp reduction
    #pragma unroll
    for (int off = 16; off > 0; off >>= 1) {
        lsum += __shfl_down_sync(0xFFFFFFFFu, lsum, off);
        lcnt += __shfl_down_sync(0xFFFFFFFFu, lcnt, off);
    }

    __shared__ float s_sum[NTHREADS / 32];
    __shared__ float s_cnt[NTHREADS / 32];
    __shared__ bool  s_last;
    const int warp = tid >> 5;
    const int lane = tid & 31;
    if (lane == 0) { s_sum[warp] = lsum; s_cnt[warp] = lcnt; }
    __syncthreads();

    if (tid == 0) {
        float vs = 0.0f, vc = 0.0f;
        #pragma unroll
        for (int w = 0; w < NTHREADS / 32; ++w) { vs += s_sum[w]; vc += s_cnt[w]; }
        g_sum[bid] = vs;
        g_cnt[bid] = vc;
        __threadfence();                       // publish partials
        unsigned old = atomicAdd(&g_ticket, 1u);
        s_last = (old == NBLOCKS - 1);
    }
    __syncthreads();

    // Last-arriving block finalizes: deterministic ordered reduction of partials.
    if (s_last) {
        // 128 threads read 64 partials: threads 0..63 read sums, 64..127 read counts.
        float v = 0.0f;
        if (tid < NBLOCKS)            v = g_sum[tid];
        else if (tid < 2 * NBLOCKS)   v = g_cnt[tid - NBLOCKS];

        // reduce within each half-warp-group via shared
        __shared__ float s_all[2 * NBLOCKS];
        s_all[tid < 2 * NBLOCKS ? tid : 0] = (tid < 2 * NBLOCKS) ? v : 0.0f;
        __syncthreads();

        if (tid == 0) {
            float vs = 0.0f, vc = 0.0f;
            #pragma unroll
            for (int i = 0; i < NBLOCKS; ++i) vs += s_all[i];
            #pragma unroll
            for (int i = 0; i < NBLOCKS; ++i) vc += s_all[NBLOCKS + i];
            result[0] = vs / vc;
            g_ticket = 0;                      // reset for next graph replay
        }
    }
}

extern "C" void kernel_launch(void* const* d_in, const int* in_sizes, int n_in,
                              void* d_out, int out_size)
{
    const float* probs  = (const float*)d_in[0];
    const int*   target = (const int*)d_in[1];
    float*       result = (float*)d_out;

    nll_gather_kernel<<<NBLOCKS, NTHREADS>>>(probs, target, result);
}